// round 17
// baseline (speedup 1.0000x reference)
#include <cuda_runtime.h>
#include <cuda_fp16.h>
#include <stdint.h>
#include <math.h>

// ---------------------------------------------------------------------------
// Problem constants
// ---------------------------------------------------------------------------
#define T_TOK 1024
#define D_DIM 2048
#define N_HEADS 32
#define K_HEADS 8
#define H_DIM 64
#define SEQ_LEN 256
#define KDIM 2048
#define NCHUNKS 64           // KDIM / 32
#define LOG2_THETA 18.93156856932417f

// ---------------------------------------------------------------------------
// Scratch (device globals; allocation is forbidden)
// ---------------------------------------------------------------------------
__device__ __align__(256) float g_q[T_TOK * N_HEADS * H_DIM];
__device__ __align__(256) float g_k[T_TOK * K_HEADS * H_DIM];
__device__ __align__(256) float g_v[T_TOK * K_HEADS * H_DIM];

__device__ __align__(256) __half g_xh[T_TOK * D_DIM];      // x as fp16
__device__ __align__(256) __half g_ah[T_TOK * 2048];       // att output as fp16

// ---------------------------------------------------------------------------
// PTX helpers (family-agnostic only: ldmatrix / mma.sync / cp.async)
// ---------------------------------------------------------------------------
__device__ __forceinline__ uint32_t smem_to_u32(const void* p) {
    uint32_t a;
    asm("{ .reg .u64 t; cvta.to.shared.u64 t, %1; cvt.u32.u64 %0, t; }"
        : "=r"(a) : "l"(p));
    return a;
}

__device__ __forceinline__ void ldsm_x4(uint32_t& r0, uint32_t& r1,
                                        uint32_t& r2, uint32_t& r3, uint32_t addr) {
    asm volatile("ldmatrix.sync.aligned.m8n8.x4.shared.b16 {%0,%1,%2,%3}, [%4];"
                 : "=r"(r0), "=r"(r1), "=r"(r2), "=r"(r3) : "r"(addr));
}
__device__ __forceinline__ void ldsm_x4_trans(uint32_t& r0, uint32_t& r1,
                                              uint32_t& r2, uint32_t& r3, uint32_t addr) {
    asm volatile("ldmatrix.sync.aligned.m8n8.x4.trans.shared.b16 {%0,%1,%2,%3}, [%4];"
                 : "=r"(r0), "=r"(r1), "=r"(r2), "=r"(r3) : "r"(addr));
}

__device__ __forceinline__ void mma_fp16(float* d, const uint32_t* a,
                                         uint32_t b0, uint32_t b1) {
    asm volatile(
        "mma.sync.aligned.m16n8k16.row.col.f32.f16.f16.f32 "
        "{%0,%1,%2,%3}, {%4,%5,%6,%7}, {%8,%9}, {%0,%1,%2,%3};"
        : "+f"(d[0]), "+f"(d[1]), "+f"(d[2]), "+f"(d[3])
        : "r"(a[0]), "r"(a[1]), "r"(a[2]), "r"(a[3]), "r"(b0), "r"(b1));
}

#define CP_ASYNC_16(dst, src) \
    asm volatile("cp.async.cg.shared.global [%0], [%1], 16;" :: "r"(dst), "l"(src))
#define CP_COMMIT() asm volatile("cp.async.commit_group;" ::: "memory")
#define CP_WAIT_1()  asm volatile("cp.async.wait_group 1;" ::: "memory")
#define CP_WAIT_0()  asm volatile("cp.async.wait_group 0;" ::: "memory")

// ---------------------------------------------------------------------------
// GEMM smem geometry: fp16 A tile + fp16 B tile + fp32 B staging, x2 buffers
// ---------------------------------------------------------------------------
#define AROW_B 80
#define ATILE_B (128 * AROW_B)          // 10240
#define BROW_B 272
#define BTILE_B (32 * BROW_B)           // 8704 (fp16 B tile)
#define BSROW_B 528                     // 128 floats (512B) + 16B pad
#define BSTILE_B (32 * BSROW_B)         // 16896 (fp32 staging)
#define BUF_B (ATILE_B + BTILE_B + BSTILE_B)   // 35840
#define GEMM_SMEM_BYTES (2 * BUF_B)            // 71680

// ---------------------------------------------------------------------------
// Prep: only x -> fp16 (weights are converted inside the GEMMs)
// ---------------------------------------------------------------------------
__global__ void __launch_bounds__(256) cvt_x_kernel(const float* __restrict__ x)
{
    int i = blockIdx.x * blockDim.x + threadIdx.x;   // 0..262143 (units of 8)
    float4 v0 = ((const float4*)x)[2 * i];
    float4 v1 = ((const float4*)x)[2 * i + 1];
    __half2 h[4];
    h[0] = __floats2half2_rn(v0.x, v0.y);
    h[1] = __floats2half2_rn(v0.z, v0.w);
    h[2] = __floats2half2_rn(v1.x, v1.y);
    h[3] = __floats2half2_rn(v1.z, v1.w);
    ((float4*)g_xh)[i] = *(float4*)h;
}

// ---------------------------------------------------------------------------
// HMMA fp16 GEMM with in-kernel fp32->fp16 B conversion.
// A [M][2048] fp16 row-major; B [2048][ldn] fp32 row-major [k][n].
// CTA tile 128x128, BK=32, 256 threads = 8 warps (2x4), warp tile 64x32.
// ---------------------------------------------------------------------------
__device__ __forceinline__ void gemm_hmma_body(
    const __half* __restrict__ A, const float* __restrict__ B,
    float* __restrict__ C, int ldn, int rowBlock, int colBlock)
{
    extern __shared__ char smem[];
    const uint32_t sbase = smem_to_u32(smem);
    const int tid  = threadIdx.x;
    const int warp = tid >> 5;
    const int lane = tid & 31;
    const int warpM = (warp & 1) * 64;
    const int warpN = (warp >> 1) * 32;

    const size_t aRow0 = (size_t)rowBlock * 128;
    const int n0 = colBlock * 128;

    float acc[4][4][4];
    #pragma unroll
    for (int i = 0; i < 4; i++)
        #pragma unroll
        for (int j = 0; j < 4; j++)
            #pragma unroll
            for (int e = 0; e < 4; e++) acc[i][j][e] = 0.0f;

    // async load: A fp16 tile + B fp32 staging
    auto issue_load = [&](int ch) {
        const uint32_t base = sbase + (ch & 1) * BUF_B;
        const int k0 = ch * 32;
        #pragma unroll
        for (int i = 0; i < 2; i++) {
            int e = tid + i * 256;              // 0..511
            int r = e >> 2, c = e & 3;
            uint32_t dst = base + r * AROW_B + c * 16;
            const __half* s = A + (aRow0 + r) * KDIM + k0 + c * 8;
            CP_ASYNC_16(dst, s);
        }
        #pragma unroll
        for (int i = 0; i < 4; i++) {
            int e = tid + i * 256;              // 0..1023
            int r = e >> 5, c = e & 31;         // row 0..31, 16B chunk 0..31
            uint32_t dst = base + ATILE_B + BTILE_B + r * BSROW_B + c * 16;
            const float* s = B + (size_t)(k0 + r) * ldn + n0 + c * 4;
            CP_ASYNC_16(dst, s);
        }
        CP_COMMIT();
    };

    issue_load(0);

    for (int ch = 0; ch < NCHUNKS; ch++) {
        if (ch + 1 < NCHUNKS) { issue_load(ch + 1); CP_WAIT_1(); }
        else                  { CP_WAIT_0(); }
        __syncthreads();

        char* bufp = smem + (ch & 1) * BUF_B;
        const uint32_t base = sbase + (ch & 1) * BUF_B;
        const uint32_t b_base = base + ATILE_B;

        // convert B staging fp32 -> fp16 tile (16 floats per thread)
        {
            int r = tid >> 3;                   // 0..31
            int c = tid & 7;                    // 0..7 (16-float segment)
            const float4* srow = (const float4*)(bufp + ATILE_B + BTILE_B
                                                 + r * BSROW_B + c * 64);
            float4 f0 = srow[0], f1 = srow[1], f2 = srow[2], f3 = srow[3];
            __half2 h[8];
            h[0] = __floats2half2_rn(f0.x, f0.y);
            h[1] = __floats2half2_rn(f0.z, f0.w);
            h[2] = __floats2half2_rn(f1.x, f1.y);
            h[3] = __floats2half2_rn(f1.z, f1.w);
            h[4] = __floats2half2_rn(f2.x, f2.y);
            h[5] = __floats2half2_rn(f2.z, f2.w);
            h[6] = __floats2half2_rn(f3.x, f3.y);
            h[7] = __floats2half2_rn(f3.z, f3.w);
            float4* drow = (float4*)(bufp + ATILE_B + r * BROW_B + c * 32);
            drow[0] = *(float4*)&h[0];
            drow[1] = *(float4*)&h[4];
        }
        __syncthreads();

        #pragma unroll
        for (int kk = 0; kk < 2; kk++) {
            uint32_t ah[4][4], bh[8];

            const uint32_t arow = (uint32_t)(warpM + (lane & 15));
            const uint32_t acolb = (uint32_t)((kk * 16 + (lane >> 4) * 8) * 2);
            #pragma unroll
            for (int mi = 0; mi < 4; mi++) {
                uint32_t ad = base + (arow + mi * 16) * AROW_B + acolb;
                ldsm_x4(ah[mi][0], ah[mi][1], ah[mi][2], ah[mi][3], ad);
            }

            const uint32_t brow = (uint32_t)(kk * 16 + ((lane >> 3) & 1) * 8 + (lane & 7));
            #pragma unroll
            for (int g = 0; g < 2; g++) {
                const uint32_t bcolb = (uint32_t)((warpN + g * 16 + (lane >> 4) * 8) * 2);
                uint32_t off = brow * BROW_B + bcolb;
                ldsm_x4_trans(bh[4*g+0], bh[4*g+1], bh[4*g+2], bh[4*g+3], b_base + off);
            }

            #pragma unroll
            for (int mi = 0; mi < 4; mi++) {
                #pragma unroll
                for (int nj = 0; nj < 4; nj++)
                    mma_fp16(acc[mi][nj], ah[mi], bh[2 * nj], bh[2 * nj + 1]);
            }
        }
        __syncthreads();
    }

    const int mrow = (lane >> 2);
    const int ncol = (lane & 3) * 2;
    #pragma unroll
    for (int mi = 0; mi < 4; mi++) {
        #pragma unroll
        for (int nj = 0; nj < 4; nj++) {
            size_t m0 = aRow0 + warpM + mi * 16 + mrow;
            size_t nn = (size_t)(n0 + warpN + nj * 8 + ncol);
            *(float2*)(C + m0 * ldn + nn)       = make_float2(acc[mi][nj][0], acc[mi][nj][1]);
            *(float2*)(C + (m0 + 8) * ldn + nn) = make_float2(acc[mi][nj][2], acc[mi][nj][3]);
        }
    }
}

__global__ void __launch_bounds__(256, 2) qkv_tc_kernel(
    const float* __restrict__ Wq, const float* __restrict__ Wk,
    const float* __restrict__ Wv)
{
    int cb = blockIdx.x;
    if (cb < 16)
        gemm_hmma_body(g_xh, Wq, g_q, 2048, blockIdx.y, cb);
    else if (cb < 20)
        gemm_hmma_body(g_xh, Wk, g_k, 512, blockIdx.y, cb - 16);
    else
        gemm_hmma_body(g_xh, Wv, g_v, 512, blockIdx.y, cb - 20);
}

__global__ void __launch_bounds__(256, 2) oproj_tc_kernel(
    const float* __restrict__ Wo, float* __restrict__ out)
{
    gemm_hmma_body(g_ah, Wo, out, 2048, blockIdx.y, blockIdx.x);
}

// ---------------------------------------------------------------------------
// RoPE v2: one block per token; 32 (cos,sin) pairs computed once into smem.
// ---------------------------------------------------------------------------
__global__ void __launch_bounds__(256) rope_kernel(const int* __restrict__ positions)
{
    const int t = blockIdx.x;
    __shared__ float cs[32], sn[32];
    const int tid = threadIdx.x;
    if (tid < 32) {
        float pos = (float)positions[t];
        float ang = pos * exp2f(-(float)tid * (LOG2_THETA / 32.0f));
        float s, c;
        sincosf(ang, &s, &c);
        cs[tid] = c; sn[tid] = s;
    }
    __syncthreads();

    #pragma unroll
    for (int it = 0; it < 5; it++) {
        int u = tid + it * 256;
        int i  = u & 31;
        int hd = u >> 5;                 // 0..39
        float* base = (hd < 32)
            ? (g_q + ((size_t)t * N_HEADS + hd) * H_DIM)
            : (g_k + ((size_t)t * K_HEADS + (hd - 32)) * H_DIM);
        float x1 = base[i], x2 = base[i + 32];
        float c = cs[i], s = sn[i];
        base[i]      = x1 * c - x2 * s;
        base[i + 32] = x2 * c + x1 * s;
    }
}

// ---------------------------------------------------------------------------
// Tensor-core flash attention (2 MMA passes), unchanged from R10.
// ---------------------------------------------------------------------------
#define AT_LD 72
#define AT_QHI 0
#define AT_KHI (256 * AT_LD)
#define AT_VHI (AT_KHI + 64 * AT_LD)
#define ATTN_SMEM_BYTES ((256 + 2 * 64) * AT_LD * 2)   // 55296

__global__ void __launch_bounds__(256, 1) attn_tc_kernel()
{
    const int kh  = blockIdx.x;
    const int qt  = blockIdx.y;
    const int seg = qt >> 2;
    const int qti = qt & 3;
    const int nkt = qti + 1;
    const int tid  = threadIdx.x;
    const int warp = tid >> 5;
    const int lane = tid & 31;

    extern __shared__ char smem[];
    __half* sh = (__half*)smem;
    const uint32_t sb = smem_to_u32(smem);

    #pragma unroll
    for (int it = 0; it < 16; it++) {
        int idx = tid + it * 256;
        int r = idx >> 4, c4 = (idx & 15) * 4;
        int t = qt * 64 + (r & 63);
        int n = kh * 4 + (r >> 6);
        float4 v = *(const float4*)(g_q + ((size_t)t * N_HEADS + n) * H_DIM + c4);
        __half* qh = sh + AT_QHI + r * AT_LD + c4;
        *(__half2*)(qh)     = __floats2half2_rn(v.x * 0.125f, v.y * 0.125f);
        *(__half2*)(qh + 2) = __floats2half2_rn(v.z * 0.125f, v.w * 0.125f);
    }

    float m[4], lsum[4];
    #pragma unroll
    for (int s = 0; s < 4; s++) { m[s] = -1e30f; lsum[s] = 0.0f; }
    float O[2][8][4];
    #pragma unroll
    for (int mi = 0; mi < 2; mi++)
        #pragma unroll
        for (int nj = 0; nj < 8; nj++)
            #pragma unroll
            for (int e = 0; e < 4; e++) O[mi][nj][e] = 0.0f;

    for (int kt = 0; kt < nkt; kt++) {
        const int s0 = seg * 256 + kt * 64;
        __syncthreads();

        #pragma unroll
        for (int it = 0; it < 4; it++) {
            int idx = tid + it * 256;
            int r = idx >> 4, c4 = (idx & 15) * 4;
            float4 kv = *(const float4*)(g_k + ((size_t)(s0 + r) * K_HEADS + kh) * H_DIM + c4);
            float4 vv = *(const float4*)(g_v + ((size_t)(s0 + r) * K_HEADS + kh) * H_DIM + c4);
            __half* p;
            p = sh + AT_KHI + r * AT_LD + c4;
            *(__half2*)p     = __floats2half2_rn(kv.x, kv.y);
            *(__half2*)(p+2) = __floats2half2_rn(kv.z, kv.w);
            p = sh + AT_VHI + r * AT_LD + c4;
            *(__half2*)p     = __floats2half2_rn(vv.x, vv.y);
            *(__half2*)(p+2) = __floats2half2_rn(vv.z, vv.w);
        }
        __syncthreads();

        float S[2][8][4];
        #pragma unroll
        for (int mi = 0; mi < 2; mi++)
            #pragma unroll
            for (int nj = 0; nj < 8; nj++)
                #pragma unroll
                for (int e = 0; e < 4; e++) S[mi][nj][e] = 0.0f;

        #pragma unroll
        for (int kj = 0; kj < 4; kj++) {
            uint32_t qh[2][4];
            const uint32_t arow = (uint32_t)(warp * 32 + (lane & 15));
            const uint32_t acolb = (uint32_t)((kj * 16 + (lane >> 4) * 8) * 2);
            #pragma unroll
            for (int mi = 0; mi < 2; mi++) {
                uint32_t ad = sb + ((arow + mi * 16) * AT_LD) * 2 + acolb;
                ldsm_x4(qh[mi][0], qh[mi][1], qh[mi][2], qh[mi][3], ad + AT_QHI * 2);
            }
            uint32_t kbh[4][4];
            const uint32_t brow = (uint32_t)(((lane >> 4) & 1) * 8 + (lane & 7));
            const uint32_t bcolb = (uint32_t)((kj * 16 + ((lane >> 3) & 1) * 8) * 2);
            #pragma unroll
            for (int ng = 0; ng < 4; ng++) {
                uint32_t off = ((ng * 16 + brow) * AT_LD) * 2 + bcolb;
                ldsm_x4(kbh[ng][0], kbh[ng][1], kbh[ng][2], kbh[ng][3], sb + AT_KHI * 2 + off);
            }
            #pragma unroll
            for (int mi = 0; mi < 2; mi++) {
                #pragma unroll
                for (int ng = 0; ng < 4; ng++) {
                    mma_fp16(S[mi][2*ng],   qh[mi], kbh[ng][0], kbh[ng][1]);
                    mma_fp16(S[mi][2*ng+1], qh[mi], kbh[ng][2], kbh[ng][3]);
                }
            }
        }

        if (kt == qti) {
            #pragma unroll
            for (int mi = 0; mi < 2; mi++) {
                #pragma unroll
                for (int nj = 0; nj < 8; nj++) {
                    #pragma unroll
                    for (int e = 0; e < 4; e++) {
                        int tok = (warp & 1) * 32 + mi * 16 + (lane >> 2) + (e >> 1) * 8;
                        int col = nj * 8 + (lane & 3) * 2 + (e & 1);
                        if (col > tok) S[mi][nj][e] = -1e30f;
                    }
                }
            }
        }

        #pragma unroll
        for (int mi = 0; mi < 2; mi++) {
            #pragma unroll
            for (int up = 0; up < 2; up++) {
                const int slot = mi * 2 + up;
                float mx = -1e30f;
                #pragma unroll
                for (int nj = 0; nj < 8; nj++) {
                    mx = fmaxf(mx, S[mi][nj][up * 2]);
                    mx = fmaxf(mx, S[mi][nj][up * 2 + 1]);
                }
                mx = fmaxf(mx, __shfl_xor_sync(0xffffffffu, mx, 1));
                mx = fmaxf(mx, __shfl_xor_sync(0xffffffffu, mx, 2));
                float m_new = fmaxf(m[slot], mx);
                float alpha = __expf(m[slot] - m_new);
                m[slot] = m_new;
                float psum = 0.0f;
                #pragma unroll
                for (int nj = 0; nj < 8; nj++) {
                    float p0 = __expf(S[mi][nj][up * 2]     - m_new);
                    float p1 = __expf(S[mi][nj][up * 2 + 1] - m_new);
                    S[mi][nj][up * 2] = p0;
                    S[mi][nj][up * 2 + 1] = p1;
                    psum += p0 + p1;
                }
                lsum[slot] = lsum[slot] * alpha + psum;
                #pragma unroll
                for (int nj = 0; nj < 8; nj++) {
                    O[mi][nj][up * 2]     *= alpha;
                    O[mi][nj][up * 2 + 1] *= alpha;
                }
            }
        }

        #pragma unroll
        for (int g = 0; g < 4; g++) {
            uint32_t pa[2][4];
            #pragma unroll
            for (int mi = 0; mi < 2; mi++) {
                __half2 h0 = __floats2half2_rn(S[mi][2*g][0],   S[mi][2*g][1]);
                __half2 h1 = __floats2half2_rn(S[mi][2*g][2],   S[mi][2*g][3]);
                __half2 h2 = __floats2half2_rn(S[mi][2*g+1][0], S[mi][2*g+1][1]);
                __half2 h3 = __floats2half2_rn(S[mi][2*g+1][2], S[mi][2*g+1][3]);
                pa[mi][0] = *(uint32_t*)&h0; pa[mi][1] = *(uint32_t*)&h1;
                pa[mi][2] = *(uint32_t*)&h2; pa[mi][3] = *(uint32_t*)&h3;
            }
            const uint32_t vrow = (uint32_t)(g * 16 + ((lane >> 3) & 1) * 8 + (lane & 7));
            #pragma unroll
            for (int nd = 0; nd < 4; nd++) {
                const uint32_t vcolb = (uint32_t)((nd * 16 + (lane >> 4) * 8) * 2);
                uint32_t off = (vrow * AT_LD) * 2 + vcolb;
                uint32_t vh0, vh1, vh2, vh3;
                ldsm_x4_trans(vh0, vh1, vh2, vh3, sb + AT_VHI * 2 + off);
                #pragma unroll
                for (int mi = 0; mi < 2; mi++) {
                    mma_fp16(O[mi][2*nd],   pa[mi], vh0, vh1);
                    mma_fp16(O[mi][2*nd+1], pa[mi], vh2, vh3);
                }
            }
        }
    }

    float inv[4];
    #pragma unroll
    for (int s = 0; s < 4; s++) {
        float l = lsum[s];
        l += __shfl_xor_sync(0xffffffffu, l, 1);
        l += __shfl_xor_sync(0xffffffffu, l, 2);
        inv[s] = 1.0f / l;
    }

    const int hh = warp >> 1;
    const int n  = kh * 4 + hh;
    #pragma unroll
    for (int mi = 0; mi < 2; mi++) {
        #pragma unroll
        for (int up = 0; up < 2; up++) {
            const int slot = mi * 2 + up;
            int tok = qt * 64 + (warp & 1) * 32 + mi * 16 + (lane >> 2) + up * 8;
            size_t rowbase = ((size_t)tok * N_HEADS + n) * H_DIM;
            #pragma unroll
            for (int nj = 0; nj < 8; nj++) {
                int col = nj * 8 + (lane & 3) * 2;
                __half2 o2 = __floats2half2_rn(O[mi][nj][up * 2] * inv[slot],
                                               O[mi][nj][up * 2 + 1] * inv[slot]);
                *(__half2*)(g_ah + rowbase + col) = o2;
            }
        }
    }
}

// ---------------------------------------------------------------------------
extern "C" void kernel_launch(void* const* d_in, const int* in_sizes, int n_in,
                              void* d_out, int out_size)
{
    (void)in_sizes; (void)n_in; (void)out_size;
    const float* x  = (const float*)d_in[0];
    const float* Wq = (const float*)d_in[1];
    const float* Wk = (const float*)d_in[2];
    const float* Wv = (const float*)d_in[3];
    const float* Wo = (const float*)d_in[4];
    const int* pos  = (const int*)d_in[5];
    float* out = (float*)d_out;

    static bool attr_set = false;
    if (!attr_set) {
        cudaFuncSetAttribute(attn_tc_kernel,
                             cudaFuncAttributeMaxDynamicSharedMemorySize, ATTN_SMEM_BYTES);
        cudaFuncSetAttribute(qkv_tc_kernel,
                             cudaFuncAttributeMaxDynamicSharedMemorySize, GEMM_SMEM_BYTES);
        cudaFuncSetAttribute(oproj_tc_kernel,
                             cudaFuncAttributeMaxDynamicSharedMemorySize, GEMM_SMEM_BYTES);
        attr_set = true;
    }

    // 1) x -> fp16 (weights converted in-GEMM)
    cvt_x_kernel<<<T_TOK * D_DIM / 8 / 256, 256>>>(x);

    // 2) QKV projection (fp16 HMMA, in-kernel weight conversion)
    qkv_tc_kernel<<<dim3(24, 8), 256, GEMM_SMEM_BYTES>>>(Wq, Wk, Wv);

    // 3) RoPE
    rope_kernel<<<T_TOK, 256>>>(pos);

    // 4) Tensor-core flash attention -> g_ah (fp16)
    attn_tc_kernel<<<dim3(K_HEADS, 16), 256, ATTN_SMEM_BYTES>>>();

    // 5) O projection (fp16 HMMA, in-kernel weight conversion)
    oproj_tc_kernel<<<dim3(16, 8), 256, GEMM_SMEM_BYTES>>>(Wo, out);
}